// round 12
// baseline (speedup 1.0000x reference)
#include <cuda_runtime.h>
#include <math.h>

#define NCTA 128
#define TPB  512
#define XSTF 132             // xs row stride in floats (33x16B, odd -> conflict-free)
#define XBUF (64 * XSTF)

// ---------------- device scratch ----------------
__device__ float g_Wr[3072 * 2048];      // reordered recurrent weights: enc0(512)|enc1(1024)|dec0(512)|dec1(1024)
__device__ float g_h0[2 * 64 * 512];
__device__ float g_h1[2 * 64 * 512];
__device__ float g_c0[64 * 512];
__device__ float g_c1[64 * 512];
__device__ float g_en_last[64 * 512];
__device__ float g_embz_enc[128 * 2048];
__device__ float g_embz_dec[128 * 2048];
__device__ float g_enlz[64 * 2048];
__device__ float g_dec_out[64 * 256 * 512];
__device__ float g_warm_sink;
__device__ __align__(128) unsigned g_arrive[32];
__device__ __align__(128) unsigned g_flag[32];

__device__ __forceinline__ float sigmoidf_(float x) { return 1.0f / (1.0f + __expf(-x)); }

__device__ __forceinline__ void grid_bar(unsigned step) {
    __syncthreads();
    if (threadIdx.x == 0) {
        __threadfence();
        unsigned prev = atomicAdd(&g_arrive[0], 1u);
        if (prev == step * NCTA - 1u) {
            asm volatile("st.release.gpu.global.u32 [%0], %1;"
                         :: "l"(&g_flag[0]), "r"(step) : "memory");
        } else {
            unsigned v;
            while (true) {
                asm volatile("ld.acquire.gpu.global.u32 %0, [%1];"
                             : "=r"(v) : "l"(&g_flag[0]) : "memory");
                if ((int)(v - step) >= 0) break;
                __nanosleep(64);
            }
        }
    }
    __syncthreads();
}

// 128 k's: per thread 32 LDS.128 (x) + 64 LDS.128 (w, conflict-free) + 256 FFMA
__device__ __forceinline__ void compute_chunk(const float* __restrict__ xrow,
                                              const float4* __restrict__ wp,
                                              float2& acc) {
    const float4* xr = reinterpret_cast<const float4*>(xrow);
#pragma unroll
    for (int kq = 0; kq < 32; ++kq) {
        float4 xv = xr[kq];
        float4 w0 = wp[kq * 16];
        float4 w1 = wp[kq * 16 + 8];
        acc.x = fmaf(xv.x, w0.x, acc.x);
        acc.y = fmaf(xv.x, w0.y, acc.y);
        acc.x = fmaf(xv.y, w0.z, acc.x);
        acc.y = fmaf(xv.y, w0.w, acc.y);
        acc.x = fmaf(xv.z, w1.x, acc.x);
        acc.y = fmaf(xv.z, w1.y, acc.y);
        acc.x = fmaf(xv.w, w1.z, acc.x);
        acc.y = fmaf(xv.w, w1.w, acc.y);
    }
}

__device__ __forceinline__ void load4cg(const float* __restrict__ hp, int fr, int qb, float4* v) {
    const float4* p = reinterpret_cast<const float4*>(hp + fr * 512);
#pragma unroll
    for (int j = 0; j < 4; ++j) v[j] = __ldcg(p + qb + j);
}

__device__ __forceinline__ void fill_x(float* __restrict__ xb, int fr, int qb, const float4* v) {
    float4* row = reinterpret_cast<float4*>(xb + fr * XSTF);
#pragma unroll
    for (int j = 0; j < 4; ++j) row[qb + j] = v[j];
}

// ---------------- init ----------------
__global__ void init_kernel() {
    int idx = blockIdx.x * blockDim.x + threadIdx.x;
    int stride = gridDim.x * blockDim.x;
    for (int i = idx; i < 2 * 64 * 512; i += stride) { g_h0[i] = 0.f; g_h1[i] = 0.f; }
    if (idx < 32) { g_arrive[idx] = 0u; g_flag[idx] = 0u; }
}

// ---------------- warm L2 with reordered weights ----------------
__global__ void warm_kernel() {
    size_t n = (size_t)3072 * 2048 / 4;
    float acc = 0.f;
    const float4* w = (const float4*)g_Wr;
    for (size_t i = (size_t)blockIdx.x * blockDim.x + threadIdx.x; i < n;
         i += (size_t)gridDim.x * blockDim.x) {
        float4 v = __ldcg(w + i);
        acc += v.x + v.y + v.z + v.w;
    }
    if (acc == 1234567.89f) g_warm_sink = acc;  // never true; keeps loads alive
}

// ---------------- fused reorder: all 4 recurrent slabs, paired-k layout ----------------
// within-CTA slab: off = (k>>1)*32 + (c>>1)*4 + (k&1)*2 + (c&1),  c = ul*4+g
__global__ void reorder_all(const float* __restrict__ encW0, const float* __restrict__ encW1,
                            const float* __restrict__ decW0, const float* __restrict__ decW1) {
    const size_t S0 = (size_t)512 * 2048, S1 = (size_t)1024 * 2048;
    const size_t total = 2 * S0 + 2 * S1;
    for (size_t idx = (size_t)blockIdx.x * blockDim.x + threadIdx.x; idx < total;
         idx += (size_t)gridDim.x * blockDim.x) {
        const float* src; float* dst; int K; size_t o = idx;
        if (o < S0)                { src = encW0 + (size_t)256 * 2048; dst = g_Wr;               K = 512;  }
        else if (o < S0 + S1)      { o -= S0;      src = encW1;                     dst = g_Wr + S0;           K = 1024; }
        else if (o < 2 * S0 + S1)  { o -= S0 + S1; src = decW0 + (size_t)768 * 2048; dst = g_Wr + S0 + S1;     K = 512;  }
        else                       { o -= 2 * S0 + S1; src = decW1;                 dst = g_Wr + 2 * S0 + S1;  K = 1024; }
        int slab = K * 16;
        int cta = (int)(o / slab);
        int rem = (int)(o - (size_t)cta * slab);
        int k2 = rem >> 5, r5 = rem & 31;
        int c2 = r5 >> 2, low = r5 & 3;
        int k = k2 * 2 + (low >> 1);
        int c = c2 * 2 + (low & 1);
        dst[o] = src[(size_t)k * 2048 + (size_t)(c & 3) * 512 + cta * 4 + (c >> 2)];
    }
}

// ---------------- precompute GEMM: C[M,2048] = A[M,K] @ B[K,2048] (+bias), reordered col store ----------------
__global__ void __launch_bounds__(256, 1) gemm_pre(
    const float* __restrict__ A, int M, int K,
    const float* __restrict__ B, const float* __restrict__ bias,
    float* __restrict__ C)
{
    const int col0 = blockIdx.x * 128;
    __shared__ __align__(16) float As[128][33];
    __shared__ __align__(16) float Ws[32][128];
    const int tid = threadIdx.x;
    const int tc = tid & 31, rg = tid >> 5;

    float4 acc[16];
#pragma unroll
    for (int i = 0; i < 16; i++) acc[i] = make_float4(0.f, 0.f, 0.f, 0.f);

    for (int k0 = 0; k0 < K; k0 += 32) {
        for (int e = tid; e < 128 * 32; e += 256) {
            int r = e >> 5, kk = e & 31;
            As[r][kk] = (r < M) ? A[(size_t)r * K + k0 + kk] : 0.f;
        }
        for (int e = tid; e < 32 * 128; e += 256) {
            int kk = e >> 7, c = e & 127;
            Ws[kk][c] = B[(size_t)(k0 + kk) * 2048 + col0 + c];
        }
        __syncthreads();
#pragma unroll
        for (int kk = 0; kk < 32; kk++) {
            float4 w = *reinterpret_cast<const float4*>(&Ws[kk][tc * 4]);
#pragma unroll
            for (int r = 0; r < 16; r++) {
                float a = As[rg * 16 + r][kk];
                acc[r].x = fmaf(a, w.x, acc[r].x);
                acc[r].y = fmaf(a, w.y, acc[r].y);
                acc[r].z = fmaf(a, w.z, acc[r].z);
                acc[r].w = fmaf(a, w.w, acc[r].w);
            }
        }
        __syncthreads();
    }
#pragma unroll
    for (int r = 0; r < 16; r++) {
        int row = rg * 16 + r;
        if (row >= M) continue;
        float av[4] = {acc[r].x, acc[r].y, acc[r].z, acc[r].w};
#pragma unroll
        for (int q = 0; q < 4; q++) {
            int oc = col0 + tc * 4 + q;
            float val = av[q] + (bias ? bias[oc] : 0.f);
            int g = oc >> 9, u = oc & 511;
            int nc = (u >> 2) * 16 + (u & 3) * 4 + g;
            C[(size_t)row * 2048 + nc] = val;
        }
    }
}

// ================= persistent sequence kernels =================
// thread map: m = tid>>3 (batch row), cp = tid&7 (ul = cp>>1, gp = cp&1)

struct GateOut { float nc, nh; };
__device__ __forceinline__ GateOut lstm_gates(float2 acc, int gp, float c) {
    float ox = __shfl_xor_sync(0xffffffffu, acc.x, 1);
    float oy = __shfl_xor_sync(0xffffffffu, acc.y, 1);
    float zi, zj, zf, zo;
    if (gp == 0) { zi = acc.x; zj = acc.y; zf = ox;    zo = oy;    }
    else         { zi = ox;    zj = oy;    zf = acc.x; zo = acc.y; }
    GateOut r;
    r.nc = c * sigmoidf_(zf + 1.0f) + sigmoidf_(zi) * tanhf(zj);
    r.nh = tanhf(r.nc) * sigmoidf_(zo);
    return r;
}

// depth-2 pipelined phase over nch chunks with per-CTA rotation.
// sel(p) -> global pointer for physical chunk p. First call must be preceded by
// a sync that frees xs (phase_sync=true emits it before prologue STS).
template <int NCH, bool PHASE_SYNC>
__device__ __forceinline__ void gemm_phase(
    float* __restrict__ xs, const float4* __restrict__ wb,
    const float* __restrict__ srcA, const float* __restrict__ srcB, int splitp,
    int cta, int m, int qb, float2& acc)
{
    const int mask = NCH - 1;
    float4 v0[4], v1[4];
    {
        int p0 = (0 + cta) & mask;
        const float* hp0 = (p0 < splitp) ? (srcA + p0 * 128) : (srcB + (p0 - splitp) * 128);
        load4cg(hp0, m, qb, v0);
        int p1 = (1 + cta) & mask;
        const float* hp1 = (p1 < splitp) ? (srcA + p1 * 128) : (srcB + (p1 - splitp) * 128);
        load4cg(hp1, m, qb, v1);
    }
    if (PHASE_SYNC) __syncthreads();
    fill_x(xs + 0 * XBUF, m, qb, v0);
    fill_x(xs + 1 * XBUF, m, qb, v1);
#pragma unroll
    for (int i = 0; i < NCH; ++i) {
        float4 nv[4];
        const int ip2 = i + 2;
        if (ip2 < NCH) {
            int p = (ip2 + cta) & mask;
            const float* hp = (p < splitp) ? (srcA + p * 128) : (srcB + (p - splitp) * 128);
            load4cg(hp, m, qb, nv);
        }
        __syncthreads();
        {
            int p = (i + cta) & mask;
            compute_chunk(xs + (i % 3) * XBUF + m * XSTF, wb + p * 512, acc);
        }
        if (ip2 < NCH) fill_x(xs + (ip2 % 3) * XBUF, m, qb, nv);
    }
}

__global__ void __launch_bounds__(TPB, 1) encoder_kernel(
    const int* __restrict__ en_input, const int* __restrict__ en_len,
    const float* __restrict__ b1g)
{
    extern __shared__ float sm[];
    float* ws0 = sm;                 // 512*16
    float* ws1 = sm + 512 * 16;      // 1024*16
    float* xs  = sm + 1536 * 16;     // 3 * XBUF

    const int cta = blockIdx.x, tid = threadIdx.x;
    const int m = tid >> 3, cp = tid & 7;
    const int gp = cp & 1;
    const int unit = cta * 4 + (cp >> 1);
    const int qb = cp * 4;

    {
        const float4* w0g = (const float4*)(g_Wr) + (size_t)cta * (512 * 4);
        float4* s0 = (float4*)ws0;
        for (int i = tid; i < 512 * 4; i += TPB) s0[i] = w0g[i];
        const float4* w1g = (const float4*)(g_Wr + (size_t)512 * 2048) + (size_t)cta * (1024 * 4);
        float4* s1 = (float4*)ws1;
        for (int i = tid; i < 1024 * 4; i += TPB) s1[i] = w1g[i];
    }
    float2 b1 = make_float2(b1g[(2 * gp + 0) * 512 + unit], b1g[(2 * gp + 1) * 512 + unit]);
    const int mylen = en_len[m];
    const float4* w0b = reinterpret_cast<const float4*>(ws0) + cp;
    const float4* w1b = reinterpret_cast<const float4*>(ws1) + cp;

    float c0 = 0.f, c1v = 0.f, h0r = 0.f, h1r = 0.f;
    __syncthreads();

    for (int t = 0; t < 256; ++t) {
        const float* h0prev = g_h0 + ((t + 1) & 1) * (64 * 512);
        float*       h0cur  = g_h0 + (t & 1) * (64 * 512);
        const float* h1prev = g_h1 + ((t + 1) & 1) * (64 * 512);
        float*       h1cur  = g_h1 + (t & 1) * (64 * 512);

        int tok = en_input[m * 256 + t];
        float2 ez = *reinterpret_cast<const float2*>(
            g_embz_enc + (size_t)tok * 2048 + cta * 16 + cp * 2);

        // ---- layer 0: K=512 (h0prev), 4 chunks ----
        float2 acc = make_float2(0.f, 0.f);
        gemm_phase<4, true>(xs, w0b, h0prev, h0prev, 4, cta, m, qb, acc);
        acc.x += ez.x; acc.y += ez.y;
        {
            bool valid = t < mylen;
            GateOut g = lstm_gates(acc, gp, c0);
            if (valid) { c0 = g.nc; h0r = g.nh; }
            if (gp == 0) h0cur[m * 512 + unit] = h0r;
        }
        grid_bar((unsigned)(t + 1));

        // ---- layer 1: K=1024 (h0cur | h1prev), 8 chunks ----
        acc = make_float2(0.f, 0.f);
        gemm_phase<8, false>(xs, w1b, h0cur, h1prev, 4, cta, m, qb, acc);
        acc.x += b1.x; acc.y += b1.y;
        {
            bool valid = t < mylen;
            GateOut g = lstm_gates(acc, gp, c1v);
            if (valid) { c1v = g.nc; h1r = g.nh; }
            if (gp == 0) {
                if (valid) g_en_last[m * 512 + unit] = h1r;
                h1cur[m * 512 + unit] = h1r;
            }
        }
    }
    if (gp == 0) {
        g_c0[m * 512 + unit] = c0;
        g_c1[m * 512 + unit] = c1v;
    }
}

__global__ void __launch_bounds__(TPB, 1) decoder_kernel(
    const int* __restrict__ dec_input, const int* __restrict__ dec_len,
    const float* __restrict__ b1g)
{
    extern __shared__ float sm[];
    float* ws0 = sm;
    float* ws1 = sm + 512 * 16;
    float* xs  = sm + 1536 * 16;

    const int cta = blockIdx.x, tid = threadIdx.x;
    const int m = tid >> 3, cp = tid & 7;
    const int gp = cp & 1;
    const int unit = cta * 4 + (cp >> 1);
    const int qb = cp * 4;

    {
        const float4* w0g = (const float4*)(g_Wr + (size_t)1536 * 2048) + (size_t)cta * (512 * 4);
        float4* s0 = (float4*)ws0;
        for (int i = tid; i < 512 * 4; i += TPB) s0[i] = w0g[i];
        const float4* w1g = (const float4*)(g_Wr + (size_t)2048 * 2048) + (size_t)cta * (1024 * 4);
        float4* s1 = (float4*)ws1;
        for (int i = tid; i < 1024 * 4; i += TPB) s1[i] = w1g[i];
    }
    float2 b1 = make_float2(b1g[(2 * gp + 0) * 512 + unit], b1g[(2 * gp + 1) * 512 + unit]);
    const int mylen = dec_len[m];
    float2 el = *reinterpret_cast<const float2*>(
        g_enlz + (size_t)m * 2048 + cta * 16 + cp * 2);

    const float4* w0b = reinterpret_cast<const float4*>(ws0) + cp;
    const float4* w1b = reinterpret_cast<const float4*>(ws1) + cp;

    float c0 = g_c0[m * 512 + unit];
    float c1v = g_c1[m * 512 + unit];
    float h0r = g_h0[64 * 512 + m * 512 + unit];
    float h1r = g_h1[64 * 512 + m * 512 + unit];
    __syncthreads();

    for (int t = 0; t < 256; ++t) {
        const float* h0prev = g_h0 + ((t + 1) & 1) * (64 * 512);
        float*       h0cur  = g_h0 + (t & 1) * (64 * 512);
        const float* h1prev = g_h1 + ((t + 1) & 1) * (64 * 512);
        float*       h1cur  = g_h1 + (t & 1) * (64 * 512);

        int tok = dec_input[m * 256 + t];
        float2 ez = *reinterpret_cast<const float2*>(
            g_embz_dec + (size_t)tok * 2048 + cta * 16 + cp * 2);

        float2 acc = make_float2(0.f, 0.f);
        gemm_phase<4, true>(xs, w0b, h0prev, h0prev, 4, cta, m, qb, acc);
        acc.x += ez.x + el.x; acc.y += ez.y + el.y;
        {
            bool valid = t < mylen;
            GateOut g = lstm_gates(acc, gp, c0);
            if (valid) { c0 = g.nc; h0r = g.nh; }
            if (gp == 0) h0cur[m * 512 + unit] = h0r;
        }
        grid_bar((unsigned)(256 + t + 1));

        acc = make_float2(0.f, 0.f);
        gemm_phase<8, false>(xs, w1b, h0cur, h1prev, 4, cta, m, qb, acc);
        acc.x += b1.x; acc.y += b1.y;
        {
            bool valid = t < mylen;
            GateOut g = lstm_gates(acc, gp, c1v);
            if (valid) { c1v = g.nc; h1r = g.nh; }
            if (gp == 0) {
                h1cur[m * 512 + unit] = h1r;
                g_dec_out[((size_t)m * 256 + t) * 512 + unit] = valid ? h1r : 0.f;
            }
        }
    }
}

// ---------------- projection: [16384,512] @ [512,128] + bias ----------------
__global__ void __launch_bounds__(256, 1) proj_kernel(
    const float* __restrict__ projW, const float* __restrict__ projb,
    float* __restrict__ out)
{
    const int row0 = blockIdx.x * 128;
    __shared__ __align__(16) float As[128][33];
    __shared__ __align__(16) float Ws[32][128];
    const int tid = threadIdx.x;
    const int tc = tid & 31, rg = tid >> 5;

    float4 acc[16];
#pragma unroll
    for (int i = 0; i < 16; i++) acc[i] = make_float4(0.f, 0.f, 0.f, 0.f);

    for (int k0 = 0; k0 < 512; k0 += 32) {
        for (int e = tid; e < 128 * 32; e += 256) {
            int r = e >> 5, kk = e & 31;
            As[r][kk] = g_dec_out[(size_t)(row0 + r) * 512 + k0 + kk];
        }
        for (int e = tid; e < 32 * 128; e += 256) {
            int kk = e >> 7, c = e & 127;
            Ws[kk][c] = projW[(size_t)(k0 + kk) * 128 + c];
        }
        __syncthreads();
#pragma unroll
        for (int kk = 0; kk < 32; kk++) {
            float4 w = *reinterpret_cast<const float4*>(&Ws[kk][tc * 4]);
#pragma unroll
            for (int r = 0; r < 16; r++) {
                float a = As[rg * 16 + r][kk];
                acc[r].x = fmaf(a, w.x, acc[r].x);
                acc[r].y = fmaf(a, w.y, acc[r].y);
                acc[r].z = fmaf(a, w.z, acc[r].z);
                acc[r].w = fmaf(a, w.w, acc[r].w);
            }
        }
        __syncthreads();
    }
    float4 pb = *reinterpret_cast<const float4*>(&projb[tc * 4]);
#pragma unroll
    for (int r = 0; r < 16; r++) {
        int row = row0 + rg * 16 + r;
        float4 v = make_float4(acc[r].x + pb.x, acc[r].y + pb.y,
                               acc[r].z + pb.z, acc[r].w + pb.w);
        *reinterpret_cast<float4*>(&out[(size_t)row * 128 + tc * 4]) = v;
    }
}

// ---------------- launch ----------------
#define SEQ_SMEM ((1536 * 16 + 3 * XBUF) * 4)

extern "C" void kernel_launch(void* const* d_in, const int* in_sizes, int n_in,
                              void* d_out, int out_size) {
    const int*   en_input  = (const int*)d_in[0];
    const int*   en_len    = (const int*)d_in[1];
    const int*   dec_input = (const int*)d_in[2];
    const int*   dec_len   = (const int*)d_in[3];
    const float* embed     = (const float*)d_in[4];
    const float* encW0     = (const float*)d_in[5];
    const float* encb0     = (const float*)d_in[6];
    const float* encW1     = (const float*)d_in[7];
    const float* encb1     = (const float*)d_in[8];
    const float* decW0     = (const float*)d_in[9];
    const float* decb0     = (const float*)d_in[10];
    const float* decW1     = (const float*)d_in[11];
    const float* decb1     = (const float*)d_in[12];
    const float* projW     = (const float*)d_in[13];
    const float* projb     = (const float*)d_in[14];
    float* out = (float*)d_out;

    float* embz_enc; cudaGetSymbolAddress((void**)&embz_enc, g_embz_enc);
    float* embz_dec; cudaGetSymbolAddress((void**)&embz_dec, g_embz_dec);
    float* enlz;     cudaGetSymbolAddress((void**)&enlz, g_enlz);
    float* en_last;  cudaGetSymbolAddress((void**)&en_last, g_en_last);

    cudaFuncSetAttribute(encoder_kernel, cudaFuncAttributeMaxDynamicSharedMemorySize, SEQ_SMEM);
    cudaFuncSetAttribute(decoder_kernel, cudaFuncAttributeMaxDynamicSharedMemorySize, SEQ_SMEM);

    init_kernel<<<128, 256>>>();                                        // idx 0
    reorder_all<<<1024, 256>>>(encW0, encW1, decW0, decW1);             // idx 1
    gemm_pre<<<16, 256>>>(embed, 128, 256, encW0, encb0, embz_enc);     // idx 2
    gemm_pre<<<16, 256>>>(embed, 128, 256, decW0, decb0, embz_dec);     // idx 3
    warm_kernel<<<296, 256>>>();                                        // idx 4
    encoder_kernel<<<NCTA, TPB, SEQ_SMEM>>>(en_input, en_len, encb1);   // idx 5
    gemm_pre<<<16, 256>>>(en_last, 64, 512, decW0 + (size_t)256 * 2048,
                          (const float*)nullptr, enlz);                 // idx 6
    decoder_kernel<<<NCTA, TPB, SEQ_SMEM>>>(dec_input, dec_len, decb1); // idx 7
    proj_kernel<<<128, 256>>>(projW, projb, out);                       // idx 8
}

// round 13
// speedup vs baseline: 1.0035x; 1.0035x over previous
#include <cuda_runtime.h>
#include <math.h>

#define NCTA_W 128           // worker CTAs (own 16 gate-cols each)
#define NCTA_T 148           // total CTAs incl. 20 barrier helpers (grid >= 148)
#define TPB  512
#define XSTF 132             // xs row stride in floats (33x16B, odd -> conflict-free)
#define XBUF (64 * XSTF)

// ---------------- device scratch ----------------
__device__ float g_Wr[3072 * 2048];      // reordered recurrent weights: enc0(512)|enc1(1024)|dec0(512)|dec1(1024)
__device__ float g_h0[2 * 64 * 512];
__device__ float g_h1[2 * 64 * 512];
__device__ float g_c0[64 * 512];
__device__ float g_c1[64 * 512];
__device__ float g_en_last[64 * 512];
__device__ float g_embz_enc[128 * 2048];
__device__ float g_embz_dec[128 * 2048];
__device__ float g_enlz[64 * 2048];
__device__ float g_dec_out[64 * 256 * 512];
__device__ float g_warm_sink;
__device__ __align__(128) unsigned g_arrive[32];
__device__ __align__(128) unsigned g_flag[32];

__device__ __forceinline__ float sigmoidf_(float x) { return 1.0f / (1.0f + __expf(-x)); }

__device__ __forceinline__ void grid_bar(unsigned step) {
    __syncthreads();
    if (threadIdx.x == 0) {
        __threadfence();
        unsigned prev = atomicAdd(&g_arrive[0], 1u);
        if (prev == step * NCTA_T - 1u) {
            asm volatile("st.release.gpu.global.u32 [%0], %1;"
                         :: "l"(&g_flag[0]), "r"(step) : "memory");
        } else {
            unsigned v;
            while (true) {
                asm volatile("ld.acquire.gpu.global.u32 %0, [%1];"
                             : "=r"(v) : "l"(&g_flag[0]) : "memory");
                if ((int)(v - step) >= 0) break;
                __nanosleep(64);
            }
        }
    }
    __syncthreads();
}

// 128 k's: per thread 32 LDS.128 (x) + 64 LDS.128 (w, conflict-free) + 256 FFMA
__device__ __forceinline__ void compute_chunk(const float* __restrict__ xrow,
                                              const float4* __restrict__ wp,
                                              float2& acc) {
    const float4* xr = reinterpret_cast<const float4*>(xrow);
#pragma unroll
    for (int kq = 0; kq < 32; ++kq) {
        float4 xv = xr[kq];
        float4 w0 = wp[kq * 16];
        float4 w1 = wp[kq * 16 + 8];
        acc.x = fmaf(xv.x, w0.x, acc.x);
        acc.y = fmaf(xv.x, w0.y, acc.y);
        acc.x = fmaf(xv.y, w0.z, acc.x);
        acc.y = fmaf(xv.y, w0.w, acc.y);
        acc.x = fmaf(xv.z, w1.x, acc.x);
        acc.y = fmaf(xv.z, w1.y, acc.y);
        acc.x = fmaf(xv.w, w1.z, acc.x);
        acc.y = fmaf(xv.w, w1.w, acc.y);
    }
}

__device__ __forceinline__ void load4cg(const float* __restrict__ hp, int fr, int qb, float4* v) {
    const float4* p = reinterpret_cast<const float4*>(hp + fr * 512);
#pragma unroll
    for (int j = 0; j < 4; ++j) v[j] = __ldcg(p + qb + j);
}

__device__ __forceinline__ void fill_x(float* __restrict__ xb, int fr, int qb, const float4* v) {
    float4* row = reinterpret_cast<float4*>(xb + fr * XSTF);
#pragma unroll
    for (int j = 0; j < 4; ++j) row[qb + j] = v[j];
}

// ---------------- init ----------------
__global__ void init_kernel() {
    int idx = blockIdx.x * blockDim.x + threadIdx.x;
    int stride = gridDim.x * blockDim.x;
    for (int i = idx; i < 2 * 64 * 512; i += stride) { g_h0[i] = 0.f; g_h1[i] = 0.f; }
    if (idx < 32) { g_arrive[idx] = 0u; g_flag[idx] = 0u; }
}

// ---------------- warm L2 with reordered weights ----------------
__global__ void warm_kernel() {
    size_t n = (size_t)3072 * 2048 / 4;
    float acc = 0.f;
    const float4* w = (const float4*)g_Wr;
    for (size_t i = (size_t)blockIdx.x * blockDim.x + threadIdx.x; i < n;
         i += (size_t)gridDim.x * blockDim.x) {
        float4 v = __ldcg(w + i);
        acc += v.x + v.y + v.z + v.w;
    }
    if (acc == 1234567.89f) g_warm_sink = acc;
}

// ---------------- fused reorder: all 4 recurrent slabs, paired-k layout ----------------
__global__ void reorder_all(const float* __restrict__ encW0, const float* __restrict__ encW1,
                            const float* __restrict__ decW0, const float* __restrict__ decW1) {
    const size_t S0 = (size_t)512 * 2048, S1 = (size_t)1024 * 2048;
    const size_t total = 2 * S0 + 2 * S1;
    for (size_t idx = (size_t)blockIdx.x * blockDim.x + threadIdx.x; idx < total;
         idx += (size_t)gridDim.x * blockDim.x) {
        const float* src; float* dst; int K; size_t o = idx;
        if (o < S0)                { src = encW0 + (size_t)256 * 2048; dst = g_Wr;               K = 512;  }
        else if (o < S0 + S1)      { o -= S0;      src = encW1;                     dst = g_Wr + S0;           K = 1024; }
        else if (o < 2 * S0 + S1)  { o -= S0 + S1; src = decW0 + (size_t)768 * 2048; dst = g_Wr + S0 + S1;     K = 512;  }
        else                       { o -= 2 * S0 + S1; src = decW1;                 dst = g_Wr + 2 * S0 + S1;  K = 1024; }
        int slab = K * 16;
        int cta = (int)(o / slab);
        int rem = (int)(o - (size_t)cta * slab);
        int k2 = rem >> 5, r5 = rem & 31;
        int c2 = r5 >> 2, low = r5 & 3;
        int k = k2 * 2 + (low >> 1);
        int c = c2 * 2 + (low & 1);
        dst[o] = src[(size_t)k * 2048 + (size_t)(c & 3) * 512 + cta * 4 + (c >> 2)];
    }
}

// ---------------- precompute GEMM: C[M,2048] = A[M,K] @ B[K,2048] (+bias), reordered col store ----------------
__global__ void __launch_bounds__(256, 1) gemm_pre(
    const float* __restrict__ A, int M, int K,
    const float* __restrict__ B, const float* __restrict__ bias,
    float* __restrict__ C)
{
    const int col0 = blockIdx.x * 128;
    __shared__ __align__(16) float As[128][33];
    __shared__ __align__(16) float Ws[32][128];
    const int tid = threadIdx.x;
    const int tc = tid & 31, rg = tid >> 5;

    float4 acc[16];
#pragma unroll
    for (int i = 0; i < 16; i++) acc[i] = make_float4(0.f, 0.f, 0.f, 0.f);

    for (int k0 = 0; k0 < K; k0 += 32) {
        for (int e = tid; e < 128 * 32; e += 256) {
            int r = e >> 5, kk = e & 31;
            As[r][kk] = (r < M) ? A[(size_t)r * K + k0 + kk] : 0.f;
        }
        for (int e = tid; e < 32 * 128; e += 256) {
            int kk = e >> 7, c = e & 127;
            Ws[kk][c] = B[(size_t)(k0 + kk) * 2048 + col0 + c];
        }
        __syncthreads();
#pragma unroll
        for (int kk = 0; kk < 32; kk++) {
            float4 w = *reinterpret_cast<const float4*>(&Ws[kk][tc * 4]);
#pragma unroll
            for (int r = 0; r < 16; r++) {
                float a = As[rg * 16 + r][kk];
                acc[r].x = fmaf(a, w.x, acc[r].x);
                acc[r].y = fmaf(a, w.y, acc[r].y);
                acc[r].z = fmaf(a, w.z, acc[r].z);
                acc[r].w = fmaf(a, w.w, acc[r].w);
            }
        }
        __syncthreads();
    }
#pragma unroll
    for (int r = 0; r < 16; r++) {
        int row = rg * 16 + r;
        if (row >= M) continue;
        float av[4] = {acc[r].x, acc[r].y, acc[r].z, acc[r].w};
#pragma unroll
        for (int q = 0; q < 4; q++) {
            int oc = col0 + tc * 4 + q;
            float val = av[q] + (bias ? bias[oc] : 0.f);
            int g = oc >> 9, u = oc & 511;
            int nc = (u >> 2) * 16 + (u & 3) * 4 + g;
            C[(size_t)row * 2048 + nc] = val;
        }
    }
}

// ================= persistent sequence kernels =================
// thread map: m = tid>>3 (batch row), cp = tid&7 (ul = cp>>1, gp = cp&1)

struct GateOut { float nc, nh; };
__device__ __forceinline__ GateOut lstm_gates(float2 acc, int gp, float c) {
    float ox = __shfl_xor_sync(0xffffffffu, acc.x, 1);
    float oy = __shfl_xor_sync(0xffffffffu, acc.y, 1);
    float zi, zj, zf, zo;
    if (gp == 0) { zi = acc.x; zj = acc.y; zf = ox;    zo = oy;    }
    else         { zi = ox;    zj = oy;    zf = acc.x; zo = acc.y; }
    GateOut r;
    r.nc = c * sigmoidf_(zf + 1.0f) + sigmoidf_(zi) * tanhf(zj);
    r.nh = tanhf(r.nc) * sigmoidf_(zo);
    return r;
}

// depth-2 pipelined phase, ROLLED outer loop (small I$ body), cyclic 3-buffer.
template <int NCH, bool PHASE_SYNC>
__device__ __forceinline__ void gemm_phase(
    float* __restrict__ xs, const float4* __restrict__ wb,
    const float* __restrict__ srcA, const float* __restrict__ srcB, int splitp,
    int cta, int m, int qb, float2& acc)
{
    const int mask = NCH - 1;
    float4 v0[4], v1[4];
    {
        int p0 = (0 + cta) & mask;
        const float* hp0 = (p0 < splitp) ? (srcA + p0 * 128) : (srcB + (p0 - splitp) * 128);
        load4cg(hp0, m, qb, v0);
        int p1 = (1 + cta) & mask;
        const float* hp1 = (p1 < splitp) ? (srcA + p1 * 128) : (srcB + (p1 - splitp) * 128);
        load4cg(hp1, m, qb, v1);
    }
    if (PHASE_SYNC) __syncthreads();
    fill_x(xs + 0 * XBUF, m, qb, v0);
    fill_x(xs + 1 * XBUF, m, qb, v1);
    int bc = 0;                      // compute-buffer index, cycles 0,1,2
#pragma unroll 1
    for (int i = 0; i < NCH; ++i) {
        float4 nv[4];
        const bool pre = (i + 2 < NCH);
        if (pre) {
            int p = (i + 2 + cta) & mask;
            const float* hp = (p < splitp) ? (srcA + p * 128) : (srcB + (p - splitp) * 128);
            load4cg(hp, m, qb, nv);
        }
        __syncthreads();
        {
            int p = (i + cta) & mask;
            compute_chunk(xs + bc * XBUF + m * XSTF, wb + p * 512, acc);
        }
        if (pre) {
            int bw = bc + 2; if (bw >= 3) bw -= 3;
            fill_x(xs + bw * XBUF, m, qb, nv);
        }
        bc = (bc + 1 == 3) ? 0 : bc + 1;
    }
}

__global__ void __launch_bounds__(TPB, 1) encoder_kernel(
    const int* __restrict__ en_input, const int* __restrict__ en_len,
    const float* __restrict__ b1g)
{
    const int cta = blockIdx.x, tid = threadIdx.x;

    // barrier helper CTAs: keep grid >= 148, arrive at every step barrier
    if (cta >= NCTA_W) {
#pragma unroll 1
        for (int t = 0; t < 256; ++t) grid_bar((unsigned)(t + 1));
        return;
    }

    extern __shared__ float sm[];
    float* ws0 = sm;                 // 512*16
    float* ws1 = sm + 512 * 16;      // 1024*16
    float* xs  = sm + 1536 * 16;     // 3 * XBUF

    const int m = tid >> 3, cp = tid & 7;
    const int gp = cp & 1;
    const int unit = cta * 4 + (cp >> 1);
    const int qb = cp * 4;

    {
        const float4* w0g = (const float4*)(g_Wr) + (size_t)cta * (512 * 4);
        float4* s0 = (float4*)ws0;
        for (int i = tid; i < 512 * 4; i += TPB) s0[i] = w0g[i];
        const float4* w1g = (const float4*)(g_Wr + (size_t)512 * 2048) + (size_t)cta * (1024 * 4);
        float4* s1 = (float4*)ws1;
        for (int i = tid; i < 1024 * 4; i += TPB) s1[i] = w1g[i];
    }
    float2 b1 = make_float2(b1g[(2 * gp + 0) * 512 + unit], b1g[(2 * gp + 1) * 512 + unit]);
    const int mylen = en_len[m];
    const float4* w0b = reinterpret_cast<const float4*>(ws0) + cp;
    const float4* w1b = reinterpret_cast<const float4*>(ws1) + cp;

    float c0 = 0.f, c1v = 0.f, h0r = 0.f, h1r = 0.f;
    __syncthreads();

#pragma unroll 1
    for (int t = 0; t < 256; ++t) {
        const float* h0prev = g_h0 + ((t + 1) & 1) * (64 * 512);
        float*       h0cur  = g_h0 + (t & 1) * (64 * 512);
        const float* h1prev = g_h1 + ((t + 1) & 1) * (64 * 512);
        float*       h1cur  = g_h1 + (t & 1) * (64 * 512);

        int tok = en_input[m * 256 + t];
        float2 ez = *reinterpret_cast<const float2*>(
            g_embz_enc + (size_t)tok * 2048 + cta * 16 + cp * 2);

        // ---- layer 0: K=512 (h0prev), 4 chunks ----
        float2 acc = make_float2(0.f, 0.f);
        gemm_phase<4, true>(xs, w0b, h0prev, h0prev, 4, cta, m, qb, acc);
        acc.x += ez.x; acc.y += ez.y;
        {
            bool valid = t < mylen;
            GateOut g = lstm_gates(acc, gp, c0);
            if (valid) { c0 = g.nc; h0r = g.nh; }
            if (gp == 0) h0cur[m * 512 + unit] = h0r;
        }
        grid_bar((unsigned)(t + 1));

        // ---- layer 1: K=1024 (h0cur | h1prev), 8 chunks ----
        acc = make_float2(0.f, 0.f);
        gemm_phase<8, false>(xs, w1b, h0cur, h1prev, 4, cta, m, qb, acc);
        acc.x += b1.x; acc.y += b1.y;
        {
            bool valid = t < mylen;
            GateOut g = lstm_gates(acc, gp, c1v);
            if (valid) { c1v = g.nc; h1r = g.nh; }
            if (gp == 0) {
                if (valid) g_en_last[m * 512 + unit] = h1r;
                h1cur[m * 512 + unit] = h1r;
            }
        }
    }
    if (gp == 0) {
        g_c0[m * 512 + unit] = c0;
        g_c1[m * 512 + unit] = c1v;
    }
}

__global__ void __launch_bounds__(TPB, 1) decoder_kernel(
    const int* __restrict__ dec_input, const int* __restrict__ dec_len,
    const float* __restrict__ b1g)
{
    const int cta = blockIdx.x, tid = threadIdx.x;

    if (cta >= NCTA_W) {
#pragma unroll 1
        for (int t = 0; t < 256; ++t) grid_bar((unsigned)(256 + t + 1));
        return;
    }

    extern __shared__ float sm[];
    float* ws0 = sm;
    float* ws1 = sm + 512 * 16;
    float* xs  = sm + 1536 * 16;

    const int m = tid >> 3, cp = tid & 7;
    const int gp = cp & 1;
    const int unit = cta * 4 + (cp >> 1);
    const int qb = cp * 4;

    {
        const float4* w0g = (const float4*)(g_Wr + (size_t)1536 * 2048) + (size_t)cta * (512 * 4);
        float4* s0 = (float4*)ws0;
        for (int i = tid; i < 512 * 4; i += TPB) s0[i] = w0g[i];
        const float4* w1g = (const float4*)(g_Wr + (size_t)2048 * 2048) + (size_t)cta * (1024 * 4);
        float4* s1 = (float4*)ws1;
        for (int i = tid; i < 1024 * 4; i += TPB) s1[i] = w1g[i];
    }
    float2 b1 = make_float2(b1g[(2 * gp + 0) * 512 + unit], b1g[(2 * gp + 1) * 512 + unit]);
    const int mylen = dec_len[m];
    float2 el = *reinterpret_cast<const float2*>(
        g_enlz + (size_t)m * 2048 + cta * 16 + cp * 2);

    const float4* w0b = reinterpret_cast<const float4*>(ws0) + cp;
    const float4* w1b = reinterpret_cast<const float4*>(ws1) + cp;

    float c0 = g_c0[m * 512 + unit];
    float c1v = g_c1[m * 512 + unit];
    float h0r = g_h0[64 * 512 + m * 512 + unit];
    float h1r = g_h1[64 * 512 + m * 512 + unit];
    __syncthreads();

#pragma unroll 1
    for (int t = 0; t < 256; ++t) {
        const float* h0prev = g_h0 + ((t + 1) & 1) * (64 * 512);
        float*       h0cur  = g_h0 + (t & 1) * (64 * 512);
        const float* h1prev = g_h1 + ((t + 1) & 1) * (64 * 512);
        float*       h1cur  = g_h1 + (t & 1) * (64 * 512);

        int tok = dec_input[m * 256 + t];
        float2 ez = *reinterpret_cast<const float2*>(
            g_embz_dec + (size_t)tok * 2048 + cta * 16 + cp * 2);

        float2 acc = make_float2(0.f, 0.f);
        gemm_phase<4, true>(xs, w0b, h0prev, h0prev, 4, cta, m, qb, acc);
        acc.x += ez.x + el.x; acc.y += ez.y + el.y;
        {
            bool valid = t < mylen;
            GateOut g = lstm_gates(acc, gp, c0);
            if (valid) { c0 = g.nc; h0r = g.nh; }
            if (gp == 0) h0cur[m * 512 + unit] = h0r;
        }
        grid_bar((unsigned)(256 + t + 1));

        acc = make_float2(0.f, 0.f);
        gemm_phase<8, false>(xs, w1b, h0cur, h1prev, 4, cta, m, qb, acc);
        acc.x += b1.x; acc.y += b1.y;
        {
            bool valid = t < mylen;
            GateOut g = lstm_gates(acc, gp, c1v);
            if (valid) { c1v = g.nc; h1r = g.nh; }
            if (gp == 0) {
                h1cur[m * 512 + unit] = h1r;
                g_dec_out[((size_t)m * 256 + t) * 512 + unit] = valid ? h1r : 0.f;
            }
        }
    }
}

// ---------------- projection: [16384,512] @ [512,128] + bias ----------------
__global__ void __launch_bounds__(256, 1) proj_kernel(
    const float* __restrict__ projW, const float* __restrict__ projb,
    float* __restrict__ out)
{
    const int row0 = blockIdx.x * 128;
    __shared__ __align__(16) float As[128][33];
    __shared__ __align__(16) float Ws[32][128];
    const int tid = threadIdx.x;
    const int tc = tid & 31, rg = tid >> 5;

    float4 acc[16];
#pragma unroll
    for (int i = 0; i < 16; i++) acc[i] = make_float4(0.f, 0.f, 0.f, 0.f);

    for (int k0 = 0; k0 < 512; k0 += 32) {
        for (int e = tid; e < 128 * 32; e += 256) {
            int r = e >> 5, kk = e & 31;
            As[r][kk] = g_dec_out[(size_t)(row0 + r) * 512 + k0 + kk];
        }
        for (int e = tid; e < 32 * 128; e += 256) {
            int kk = e >> 7, c = e & 127;
            Ws[kk][c] = projW[(size_t)(k0 + kk) * 128 + c];
        }
        __syncthreads();
#pragma unroll
        for (int kk = 0; kk < 32; kk++) {
            float4 w = *reinterpret_cast<const float4*>(&Ws[kk][tc * 4]);
#pragma unroll
            for (int r = 0; r < 16; r++) {
                float a = As[rg * 16 + r][kk];
                acc[r].x = fmaf(a, w.x, acc[r].x);
                acc[r].y = fmaf(a, w.y, acc[r].y);
                acc[r].z = fmaf(a, w.z, acc[r].z);
                acc[r].w = fmaf(a, w.w, acc[r].w);
            }
        }
        __syncthreads();
    }
    float4 pb = *reinterpret_cast<const float4*>(&projb[tc * 4]);
#pragma unroll
    for (int r = 0; r < 16; r++) {
        int row = row0 + rg * 16 + r;
        float4 v = make_float4(acc[r].x + pb.x, acc[r].y + pb.y,
                               acc[r].z + pb.z, acc[r].w + pb.w);
        *reinterpret_cast<float4*>(&out[(size_t)row * 128 + tc * 4]) = v;
    }
}

// ---------------- launch ----------------
#define SEQ_SMEM ((1536 * 16 + 3 * XBUF) * 4)

extern "C" void kernel_launch(void* const* d_in, const int* in_sizes, int n_in,
                              void* d_out, int out_size) {
    const int*   en_input  = (const int*)d_in[0];
    const int*   en_len    = (const int*)d_in[1];
    const int*   dec_input = (const int*)d_in[2];
    const int*   dec_len   = (const int*)d_in[3];
    const float* embed     = (const float*)d_in[4];
    const float* encW0     = (const float*)d_in[5];
    const float* encb0     = (const float*)d_in[6];
    const float* encW1     = (const float*)d_in[7];
    const float* encb1     = (const float*)d_in[8];
    const float* decW0     = (const float*)d_in[9];
    const float* decb0     = (const float*)d_in[10];
    const float* decW1     = (const float*)d_in[11];
    const float* decb1     = (const float*)d_in[12];
    const float* projW     = (const float*)d_in[13];
    const float* projb     = (const float*)d_in[14];
    float* out = (float*)d_out;

    float* embz_enc; cudaGetSymbolAddress((void**)&embz_enc, g_embz_enc);
    float* embz_dec; cudaGetSymbolAddress((void**)&embz_dec, g_embz_dec);
    float* enlz;     cudaGetSymbolAddress((void**)&enlz, g_enlz);
    float* en_last;  cudaGetSymbolAddress((void**)&en_last, g_en_last);

    cudaFuncSetAttribute(encoder_kernel, cudaFuncAttributeMaxDynamicSharedMemorySize, SEQ_SMEM);
    cudaFuncSetAttribute(decoder_kernel, cudaFuncAttributeMaxDynamicSharedMemorySize, SEQ_SMEM);

    init_kernel<<<128, 256>>>();                                          // idx 0
    reorder_all<<<1024, 256>>>(encW0, encW1, decW0, decW1);               // idx 1
    gemm_pre<<<16, 256>>>(embed, 128, 256, encW0, encb0, embz_enc);       // idx 2
    gemm_pre<<<16, 256>>>(embed, 128, 256, decW0, decb0, embz_dec);       // idx 3
    warm_kernel<<<296, 256>>>();                                          // idx 4
    encoder_kernel<<<NCTA_T, TPB, SEQ_SMEM>>>(en_input, en_len, encb1);   // idx 5
    gemm_pre<<<16, 256>>>(en_last, 64, 512, decW0 + (size_t)256 * 2048,
                          (const float*)nullptr, enlz);                   // idx 6
    decoder_kernel<<<NCTA_T, TPB, SEQ_SMEM>>>(dec_input, dec_len, decb1); // idx 7
    proj_kernel<<<128, 256>>>(projW, projb, out);                         // idx 8
}